// round 4
// baseline (speedup 1.0000x reference)
#include <cuda_runtime.h>
#include <cstdint>
#include <cstddef>

// ---------------------------------------------------------------------------
// Problem constants
// ---------------------------------------------------------------------------
static constexpr int NW = 50000;   // words
static constexpr int NT = 2000;    // topics
static constexpr int ND = 50000;   // docs
static constexpr int DO_ = 128;    // output dim

// ---------------------------------------------------------------------------
// Scratch layout (floats) inside one big __device__ array (no allocations!)
// ---------------------------------------------------------------------------
static constexpr size_t OFF_WH_WW = 0;
static constexpr size_t OFF_WH_WT = OFF_WH_WW + (size_t)NW * DO_;
static constexpr size_t OFF_WH_WD = OFF_WH_WT + (size_t)NW * DO_;
static constexpr size_t OFF_WH_TD = OFF_WH_WD + (size_t)NW * DO_;
static constexpr size_t OFF_WH_TT = OFF_WH_TD + (size_t)NT * DO_;
static constexpr size_t OFF_S_WW  = OFF_WH_TT + (size_t)NT * DO_;
static constexpr size_t OFF_S_WT  = OFF_S_WW  + (size_t)NW * DO_;
static constexpr size_t OFF_S_WD  = OFF_S_WT  + (size_t)NT * DO_;
static constexpr size_t OFF_S_TD  = OFF_S_WD  + (size_t)ND * DO_;
static constexpr size_t OFF_S_TT  = OFF_S_TD  + (size_t)ND * DO_;
static constexpr size_t OFF_DEG_WW = OFF_S_TT + (size_t)NT * DO_;
static constexpr size_t OFF_DEG_WT = OFF_DEG_WW + NW;
static constexpr size_t OFF_DEG_WD = OFF_DEG_WT + NT;
static constexpr size_t OFF_DEG_TD = OFF_DEG_WD + ND;
static constexpr size_t OFF_DEG_TT = OFF_DEG_TD + ND;
static constexpr size_t TOTAL_F    = OFF_DEG_TT + NT;
static constexpr size_t TOTAL_F_PAD = (TOTAL_F + 3) & ~(size_t)3;

__device__ __align__(16) float g_scratch[TOTAL_F_PAD];

// ---------------------------------------------------------------------------
// Zero the accumulator + degree region (everything from OFF_S_WW up)
// ---------------------------------------------------------------------------
__global__ void zero_accum_kernel() {
    const size_t n4 = (TOTAL_F_PAD - OFF_S_WW) / 4;
    float4* p = reinterpret_cast<float4*>(g_scratch + OFF_S_WW);
    size_t i = (size_t)blockIdx.x * blockDim.x + threadIdx.x;
    size_t stride = (size_t)gridDim.x * blockDim.x;
    float4 z = make_float4(0.f, 0.f, 0.f, 0.f);
    for (; i < n4; i += stride) p[i] = z;
}

// ---------------------------------------------------------------------------
// Fused multi-relation SGEMM + bias:
//   For r = blockIdx.y: C_r[M,128] = A[M,K] @ W_r[K,128] + b_r
// A is shared across relations -> L2 reuse of A tiles across y-blocks.
// BM=128, BN=128, BK=16, 256 threads, 8x8 per thread.
// ---------------------------------------------------------------------------
#define BM 128
#define BN 128
#define BK 16

struct GemmRel {
    const float* W;
    const float* bias;
    size_t c_off;
};

__global__ __launch_bounds__(256, 2)
void sgemm_bias_multi_kernel(const float* __restrict__ A,
                             GemmRel r0, GemmRel r1, GemmRel r2,
                             int M, int K) {
    __shared__ float As[BK][BM + 4];   // +4 pad: avoid store bank conflicts
    __shared__ float Bs[BK][BN];

    const GemmRel rel = (blockIdx.y == 0) ? r0 : (blockIdx.y == 1) ? r1 : r2;
    const float* __restrict__ W    = rel.W;
    const float* __restrict__ bias = rel.bias;

    const int tid = threadIdx.x;
    const int block_row = blockIdx.x * BM;
    const int tx = tid & 15;    // 0..15 (col group)
    const int ty = tid >> 4;    // 0..15 (row group)

    float acc[8][8];
    #pragma unroll
    for (int i = 0; i < 8; i++)
        #pragma unroll
        for (int j = 0; j < 8; j++) acc[i][j] = 0.f;

    for (int k0 = 0; k0 < K; k0 += BK) {
        // --- load A tile: 128 rows x 16 cols, store transposed As[k][m] ---
        #pragma unroll
        for (int l = 0; l < 2; l++) {
            int idx = tid + l * 256;        // 0..511  (512 float4 total)
            int r   = idx >> 2;             // 0..127
            int c4  = idx & 3;              // 0..3
            int grow = block_row + r;
            float4 v = make_float4(0.f, 0.f, 0.f, 0.f);
            if (grow < M)
                v = *reinterpret_cast<const float4*>(A + (size_t)grow * K + k0 + c4 * 4);
            As[c4 * 4 + 0][r] = v.x;
            As[c4 * 4 + 1][r] = v.y;
            As[c4 * 4 + 2][r] = v.z;
            As[c4 * 4 + 3][r] = v.w;
        }
        // --- load W tile: 16 rows x 128 cols (row-major, direct) ---
        #pragma unroll
        for (int l = 0; l < 2; l++) {
            int idx = tid + l * 256;        // 0..511
            int r   = idx >> 5;             // 0..15
            int c4  = idx & 31;             // 0..31
            float4 v = *reinterpret_cast<const float4*>(W + (size_t)(k0 + r) * BN + c4 * 4);
            *reinterpret_cast<float4*>(&Bs[r][c4 * 4]) = v;
        }
        __syncthreads();

        #pragma unroll
        for (int k = 0; k < BK; k++) {
            float4 a0 = *reinterpret_cast<const float4*>(&As[k][ty * 8]);
            float4 a1 = *reinterpret_cast<const float4*>(&As[k][ty * 8 + 4]);
            float4 b0 = *reinterpret_cast<const float4*>(&Bs[k][tx * 8]);
            float4 b1 = *reinterpret_cast<const float4*>(&Bs[k][tx * 8 + 4]);
            float a[8] = {a0.x, a0.y, a0.z, a0.w, a1.x, a1.y, a1.z, a1.w};
            float b[8] = {b0.x, b0.y, b0.z, b0.w, b1.x, b1.y, b1.z, b1.w};
            #pragma unroll
            for (int i = 0; i < 8; i++)
                #pragma unroll
                for (int j = 0; j < 8; j++)
                    acc[i][j] += a[i] * b[j];
        }
        __syncthreads();
    }

    // --- epilogue: add bias, write C ---
    float* C = g_scratch + rel.c_off;
    #pragma unroll
    for (int i = 0; i < 8; i++) {
        int grow = block_row + ty * 8 + i;
        if (grow < M) {
            #pragma unroll
            for (int j = 0; j < 8; j += 4) {
                int col = tx * 8 + j;
                float4 v;
                v.x = acc[i][j]     + bias[col];
                v.y = acc[i][j + 1] + bias[col + 1];
                v.z = acc[i][j + 2] + bias[col + 2];
                v.w = acc[i][j + 3] + bias[col + 3];
                *reinterpret_cast<float4*>(C + (size_t)grow * BN + col) = v;
            }
        }
    }
}

// ---------------------------------------------------------------------------
// Edge aggregation: one warp per edge.
//   s[dst] += Wh[src] * w   (red.global.add.v4.f32, 32 lanes x float4 = 128B)
//   deg[dst] += 1           (lane 0)
// ---------------------------------------------------------------------------
__global__ void edge_agg_kernel(size_t wh_off,
                                const int* __restrict__ src,
                                const int* __restrict__ dst,
                                const float* __restrict__ w,
                                size_t s_off, size_t deg_off, int E) {
    int gw   = (int)(((size_t)blockIdx.x * blockDim.x + threadIdx.x) >> 5);
    int lane = threadIdx.x & 31;
    if (gw >= E) return;

    int   sn = __ldg(src + gw);
    int   dn = __ldg(dst + gw);
    float ew = __ldg(w + gw);

    const float4* srow = reinterpret_cast<const float4*>(g_scratch + wh_off + (size_t)sn * DO_);
    float4 v = __ldg(srow + lane);
    v.x *= ew; v.y *= ew; v.z *= ew; v.w *= ew;

    float* addr = g_scratch + s_off + (size_t)dn * DO_ + lane * 4;
    asm volatile("red.global.add.v4.f32 [%0], {%1, %2, %3, %4};"
                 :: "l"(addr), "f"(v.x), "f"(v.y), "f"(v.z), "f"(v.w)
                 : "memory");

    if (lane == 0) atomicAdd(g_scratch + deg_off + dn, 1.0f);
}

// ---------------------------------------------------------------------------
// Finalize: out rows [0,50000) = word, [50000,52000) = topic, [52000,102000) = doc
// word  = s_ww/deg ;  topic = s_wt/deg + s_tt/deg ;  doc = s_wd/deg + s_td/deg
// (deg==0 -> s==0 -> result 0, so 1/deg with guard is exact)
// ---------------------------------------------------------------------------
__global__ void finalize_kernel(float* __restrict__ out) {
    int t = blockIdx.x * blockDim.x + threadIdx.x;       // one float4 per thread
    const int total = (NW + NT + ND) * (DO_ / 4);        // 102000 * 32
    if (t >= total) return;
    int row = t >> 5;
    int c   = (t & 31) * 4;

    float4 v;
    if (row < NW) {
        float d = g_scratch[OFF_DEG_WW + row];
        float inv = d > 0.f ? 1.0f / d : 0.0f;
        float4 s = *reinterpret_cast<const float4*>(g_scratch + OFF_S_WW + (size_t)row * DO_ + c);
        v = make_float4(s.x * inv, s.y * inv, s.z * inv, s.w * inv);
    } else if (row < NW + NT) {
        int r = row - NW;
        float d1 = g_scratch[OFF_DEG_WT + r];
        float d2 = g_scratch[OFF_DEG_TT + r];
        float i1 = d1 > 0.f ? 1.0f / d1 : 0.0f;
        float i2 = d2 > 0.f ? 1.0f / d2 : 0.0f;
        float4 s1 = *reinterpret_cast<const float4*>(g_scratch + OFF_S_WT + (size_t)r * DO_ + c);
        float4 s2 = *reinterpret_cast<const float4*>(g_scratch + OFF_S_TT + (size_t)r * DO_ + c);
        v = make_float4(s1.x * i1 + s2.x * i2, s1.y * i1 + s2.y * i2,
                        s1.z * i1 + s2.z * i2, s1.w * i1 + s2.w * i2);
    } else {
        int r = row - NW - NT;
        float d1 = g_scratch[OFF_DEG_WD + r];
        float d2 = g_scratch[OFF_DEG_TD + r];
        float i1 = d1 > 0.f ? 1.0f / d1 : 0.0f;
        float i2 = d2 > 0.f ? 1.0f / d2 : 0.0f;
        float4 s1 = *reinterpret_cast<const float4*>(g_scratch + OFF_S_WD + (size_t)r * DO_ + c);
        float4 s2 = *reinterpret_cast<const float4*>(g_scratch + OFF_S_TD + (size_t)r * DO_ + c);
        v = make_float4(s1.x * i1 + s2.x * i2, s1.y * i1 + s2.y * i2,
                        s1.z * i1 + s2.z * i2, s1.w * i1 + s2.w * i2);
    }
    *reinterpret_cast<float4*>(out + (size_t)row * DO_ + c) = v;
}

// ---------------------------------------------------------------------------
// Launch
// ---------------------------------------------------------------------------
extern "C" void kernel_launch(void* const* d_in, const int* in_sizes, int n_in,
                              void* d_out, int out_size) {
    const float* feat_word  = (const float*)d_in[0];
    const float* feat_topic = (const float*)d_in[1];

    const int*   ww_src = (const int*)d_in[2];
    const int*   ww_dst = (const int*)d_in[3];
    const float* ww_w   = (const float*)d_in[4];
    const int*   wt_src = (const int*)d_in[5];
    const int*   wt_dst = (const int*)d_in[6];
    const float* wt_w   = (const float*)d_in[7];
    const int*   wd_src = (const int*)d_in[8];
    const int*   wd_dst = (const int*)d_in[9];
    const float* wd_w   = (const float*)d_in[10];
    const int*   td_src = (const int*)d_in[11];
    const int*   td_dst = (const int*)d_in[12];
    const float* td_w   = (const float*)d_in[13];
    const int*   tt_src = (const int*)d_in[14];
    const int*   tt_dst = (const int*)d_in[15];
    const float* tt_w   = (const float*)d_in[16];

    const float* W_ww = (const float*)d_in[17];
    const float* b_ww = (const float*)d_in[18];
    const float* W_wt = (const float*)d_in[19];
    const float* b_wt = (const float*)d_in[20];
    const float* W_wd = (const float*)d_in[21];
    const float* b_wd = (const float*)d_in[22];
    const float* W_td = (const float*)d_in[23];
    const float* b_td = (const float*)d_in[24];
    const float* W_tt = (const float*)d_in[25];
    const float* b_tt = (const float*)d_in[26];

    const int E_ww = in_sizes[2];
    const int E_wt = in_sizes[5];
    const int E_wd = in_sizes[8];
    const int E_td = in_sizes[11];
    const int E_tt = in_sizes[14];

    // 1) zero accumulators + degrees
    zero_accum_kernel<<<1184, 256>>>();

    // 2) projections (fused per source node type)
    const int gw = (NW + BM - 1) / BM;   // 391
    const int gt = (NT + BM - 1) / BM;   // 16
    {
        GemmRel r0{W_ww, b_ww, OFF_WH_WW};
        GemmRel r1{W_wt, b_wt, OFF_WH_WT};
        GemmRel r2{W_wd, b_wd, OFF_WH_WD};
        dim3 grid(gw, 3);
        sgemm_bias_multi_kernel<<<grid, 256>>>(feat_word, r0, r1, r2, NW, 256);
    }
    {
        GemmRel r0{W_td, b_td, OFF_WH_TD};
        GemmRel r1{W_tt, b_tt, OFF_WH_TT};
        GemmRel r2{W_tt, b_tt, OFF_WH_TT};   // slot unused: gridDim.y == 2
        dim3 grid(gt, 2);
        sgemm_bias_multi_kernel<<<grid, 256>>>(feat_topic, r0, r1, r2, NT, 128);
    }

    // 3) edge aggregation (one warp per edge)
    auto agg_blocks = [](int E) { return (E + 7) / 8; };   // 8 warps per 256-thread block
    edge_agg_kernel<<<agg_blocks(E_ww), 256>>>(OFF_WH_WW, ww_src, ww_dst, ww_w, OFF_S_WW, OFF_DEG_WW, E_ww);
    edge_agg_kernel<<<agg_blocks(E_wt), 256>>>(OFF_WH_WT, wt_src, wt_dst, wt_w, OFF_S_WT, OFF_DEG_WT, E_wt);
    edge_agg_kernel<<<agg_blocks(E_wd), 256>>>(OFF_WH_WD, wd_src, wd_dst, wd_w, OFF_S_WD, OFF_DEG_WD, E_wd);
    edge_agg_kernel<<<agg_blocks(E_td), 256>>>(OFF_WH_TD, td_src, td_dst, td_w, OFF_S_TD, OFF_DEG_TD, E_td);
    edge_agg_kernel<<<agg_blocks(E_tt), 256>>>(OFF_WH_TT, tt_src, tt_dst, tt_w, OFF_S_TT, OFF_DEG_TT, E_tt);

    // 4) finalize
    const int total4 = (NW + NT + ND) * (DO_ / 4);
    finalize_kernel<<<(total4 + 255) / 256, 256>>>((float*)d_out);
}

// round 5
// speedup vs baseline: 1.2145x; 1.2145x over previous
#include <cuda_runtime.h>
#include <cstdint>
#include <cstddef>

// ---------------------------------------------------------------------------
// Problem constants
// ---------------------------------------------------------------------------
static constexpr int NW = 50000;   // words
static constexpr int NT = 2000;    // topics
static constexpr int ND = 50000;   // docs
static constexpr int DO_ = 128;    // output dim

// ---------------------------------------------------------------------------
// Scratch layout (floats) inside one big __device__ array (no allocations!)
// ---------------------------------------------------------------------------
static constexpr size_t OFF_WH_WW = 0;
static constexpr size_t OFF_WH_WT = OFF_WH_WW + (size_t)NW * DO_;
static constexpr size_t OFF_WH_WD = OFF_WH_WT + (size_t)NW * DO_;
static constexpr size_t OFF_WH_TD = OFF_WH_WD + (size_t)NW * DO_;
static constexpr size_t OFF_WH_TT = OFF_WH_TD + (size_t)NT * DO_;
static constexpr size_t OFF_S_WW  = OFF_WH_TT + (size_t)NT * DO_;
static constexpr size_t OFF_S_WT  = OFF_S_WW  + (size_t)NW * DO_;
static constexpr size_t OFF_S_WD  = OFF_S_WT  + (size_t)NT * DO_;
static constexpr size_t OFF_S_TD  = OFF_S_WD  + (size_t)ND * DO_;
static constexpr size_t OFF_S_TT  = OFF_S_TD  + (size_t)ND * DO_;
static constexpr size_t OFF_DEG_WW = OFF_S_TT + (size_t)NT * DO_;
static constexpr size_t OFF_DEG_WT = OFF_DEG_WW + NW;
static constexpr size_t OFF_DEG_WD = OFF_DEG_WT + NT;
static constexpr size_t OFF_DEG_TD = OFF_DEG_WD + ND;
static constexpr size_t OFF_DEG_TT = OFF_DEG_TD + ND;
static constexpr size_t TOTAL_F    = OFF_DEG_TT + NT;
static constexpr size_t TOTAL_F_PAD = (TOTAL_F + 3) & ~(size_t)3;

__device__ __align__(16) float g_scratch[TOTAL_F_PAD];

// ---------------------------------------------------------------------------
// Zero the accumulator + degree region
// ---------------------------------------------------------------------------
__global__ void zero_accum_kernel() {
    const size_t n4 = (TOTAL_F_PAD - OFF_S_WW) / 4;
    float4* p = reinterpret_cast<float4*>(g_scratch + OFF_S_WW);
    size_t i = (size_t)blockIdx.x * blockDim.x + threadIdx.x;
    size_t stride = (size_t)gridDim.x * blockDim.x;
    float4 z = make_float4(0.f, 0.f, 0.f, 0.f);
    for (; i < n4; i += stride) p[i] = z;
}

// ---------------------------------------------------------------------------
// tf32 tensor-core GEMM + bias (fused over up to 3 relations via blockIdx.y)
//   C_r[M,128] = A[M,K] @ W_r[K,128] + b_r
// BM=128, BN=128, BK=16; 256 threads = 8 warps (2 x 4), warp tile 64x32.
// mma.sync m16n8k8 tf32, fp32 accumulate. cvt.rna.tf32 during smem staging.
// ---------------------------------------------------------------------------
#define BM 128
#define BN 128
#define BK 16

struct GemmRel {
    const float* W;
    const float* bias;
    size_t c_off;
};

__device__ __forceinline__ uint32_t f2tf32(float x) {
    uint32_t u;
    asm("cvt.rna.tf32.f32 %0, %1;" : "=r"(u) : "f"(x));
    return u;
}

__device__ __forceinline__ void mma_tf32(float c[4],
                                         uint32_t a0, uint32_t a1, uint32_t a2, uint32_t a3,
                                         uint32_t b0, uint32_t b1) {
    asm volatile("mma.sync.aligned.m16n8k8.row.col.f32.tf32.tf32.f32 "
                 "{%0,%1,%2,%3}, {%4,%5,%6,%7}, {%8,%9}, {%0,%1,%2,%3};"
                 : "+f"(c[0]), "+f"(c[1]), "+f"(c[2]), "+f"(c[3])
                 : "r"(a0), "r"(a1), "r"(a2), "r"(a3), "r"(b0), "r"(b1));
}

__global__ __launch_bounds__(256)
void gemm_tf32_multi_kernel(const float* __restrict__ A,
                            GemmRel r0, GemmRel r1, GemmRel r2,
                            int M, int K) {
    // As stored transposed [k][m], Bs row-major [k][n]; both padded +4 floats.
    __shared__ __align__(16) float As[BK][BM + 4];
    __shared__ __align__(16) float Bs[BK][BN + 4];

    const GemmRel rel = (blockIdx.y == 0) ? r0 : (blockIdx.y == 1) ? r1 : r2;
    const float* __restrict__ W    = rel.W;
    const float* __restrict__ bias = rel.bias;

    const int tid  = threadIdx.x;
    const int wid  = tid >> 5;
    const int lane = tid & 31;
    const int g    = lane >> 2;       // group id 0..7
    const int t    = lane & 3;        // thread-in-group 0..3
    const int wm   = (wid >> 2) * 64; // warp M offset: 0 or 64
    const int wn   = (wid & 3) * 32;  // warp N offset: 0,32,64,96
    const int block_row = blockIdx.x * BM;

    float acc[4][4][4];               // [mi][ni][c0..c3]
    #pragma unroll
    for (int mi = 0; mi < 4; mi++)
        #pragma unroll
        for (int ni = 0; ni < 4; ni++)
            #pragma unroll
            for (int c = 0; c < 4; c++) acc[mi][ni][c] = 0.f;

    for (int k0 = 0; k0 < K; k0 += BK) {
        // --- stage A tile: 128 rows x 16 cols -> As[k][m], tf32-converted ---
        #pragma unroll
        for (int l = 0; l < 2; l++) {
            int idx = tid + l * 256;         // 0..511
            int r   = idx >> 2;              // 0..127 (row within tile)
            int c4  = idx & 3;               // 0..3   (float4 within 16 cols)
            int grow = block_row + r;
            float4 v = make_float4(0.f, 0.f, 0.f, 0.f);
            if (grow < M)
                v = *reinterpret_cast<const float4*>(A + (size_t)grow * K + k0 + c4 * 4);
            As[c4 * 4 + 0][r] = __uint_as_float(f2tf32(v.x));
            As[c4 * 4 + 1][r] = __uint_as_float(f2tf32(v.y));
            As[c4 * 4 + 2][r] = __uint_as_float(f2tf32(v.z));
            As[c4 * 4 + 3][r] = __uint_as_float(f2tf32(v.w));
        }
        // --- stage W tile: 16 rows x 128 cols -> Bs[k][n], tf32-converted ---
        #pragma unroll
        for (int l = 0; l < 2; l++) {
            int idx = tid + l * 256;         // 0..511
            int r   = idx >> 5;              // 0..15
            int c4  = idx & 31;              // 0..31
            float4 v = *reinterpret_cast<const float4*>(W + (size_t)(k0 + r) * BN + c4 * 4);
            float4 o;
            o.x = __uint_as_float(f2tf32(v.x));
            o.y = __uint_as_float(f2tf32(v.y));
            o.z = __uint_as_float(f2tf32(v.z));
            o.w = __uint_as_float(f2tf32(v.w));
            *reinterpret_cast<float4*>(&Bs[r][c4 * 4]) = o;
        }
        __syncthreads();

        #pragma unroll
        for (int ks = 0; ks < BK; ks += 8) {
            // B fragments for 4 n-tiles
            uint32_t bf[4][2];
            #pragma unroll
            for (int ni = 0; ni < 4; ni++) {
                int n = wn + ni * 8 + g;
                bf[ni][0] = __float_as_uint(Bs[ks + t][n]);
                bf[ni][1] = __float_as_uint(Bs[ks + t + 4][n]);
            }
            // A fragments for 4 m-tiles, then mma row
            #pragma unroll
            for (int mi = 0; mi < 4; mi++) {
                int m = wm + mi * 16 + g;
                uint32_t a0 = __float_as_uint(As[ks + t][m]);
                uint32_t a1 = __float_as_uint(As[ks + t][m + 8]);
                uint32_t a2 = __float_as_uint(As[ks + t + 4][m]);
                uint32_t a3 = __float_as_uint(As[ks + t + 4][m + 8]);
                #pragma unroll
                for (int ni = 0; ni < 4; ni++)
                    mma_tf32(acc[mi][ni], a0, a1, a2, a3, bf[ni][0], bf[ni][1]);
            }
        }
        __syncthreads();
    }

    // --- epilogue: add bias, write C (float2 stores) ---
    float* C = g_scratch + rel.c_off;
    #pragma unroll
    for (int mi = 0; mi < 4; mi++) {
        #pragma unroll
        for (int ni = 0; ni < 4; ni++) {
            int col  = wn + ni * 8 + 2 * t;
            float b0 = bias[col], b1 = bias[col + 1];
            int row0 = block_row + wm + mi * 16 + g;
            int row1 = row0 + 8;
            if (row0 < M) {
                float2 v0 = make_float2(acc[mi][ni][0] + b0, acc[mi][ni][1] + b1);
                *reinterpret_cast<float2*>(C + (size_t)row0 * BN + col) = v0;
            }
            if (row1 < M) {
                float2 v1 = make_float2(acc[mi][ni][2] + b0, acc[mi][ni][3] + b1);
                *reinterpret_cast<float2*>(C + (size_t)row1 * BN + col) = v1;
            }
        }
    }
}

// ---------------------------------------------------------------------------
// Fused edge aggregation over ALL 5 relations: one warp per edge.
//   s[dst] += Wh[src] * w   (red.global.add.v4.f32)
//   deg[dst] += 1           (lane 0)
// ---------------------------------------------------------------------------
struct EdgeTable {
    const int*   src[5];
    const int*   dst[5];
    const float* w[5];
    unsigned long long wh[5];
    unsigned long long s[5];
    unsigned long long deg[5];
    int end[5];            // inclusive prefix-sum of edge counts
};

__global__ void edge_agg_fused_kernel(EdgeTable et) {
    int gw   = (int)(((size_t)blockIdx.x * blockDim.x + threadIdx.x) >> 5);
    int lane = threadIdx.x & 31;
    if (gw >= et.end[4]) return;

    int r = 0;
    #pragma unroll
    for (int i = 0; i < 4; i++) r += (gw >= et.end[i]) ? 1 : 0;
    int e = gw - (r > 0 ? et.end[r - 1] : 0);

    int   sn = __ldg(et.src[r] + e);
    int   dn = __ldg(et.dst[r] + e);
    float ew = __ldg(et.w[r] + e);

    const float4* srow = reinterpret_cast<const float4*>(g_scratch + et.wh[r] + (size_t)sn * DO_);
    float4 v = __ldg(srow + lane);
    v.x *= ew; v.y *= ew; v.z *= ew; v.w *= ew;

    float* addr = g_scratch + et.s[r] + (size_t)dn * DO_ + lane * 4;
    asm volatile("red.global.add.v4.f32 [%0], {%1, %2, %3, %4};"
                 :: "l"(addr), "f"(v.x), "f"(v.y), "f"(v.z), "f"(v.w)
                 : "memory");

    if (lane == 0) atomicAdd(g_scratch + et.deg[r] + dn, 1.0f);
}

// ---------------------------------------------------------------------------
// Finalize: word = s_ww/deg ; topic = s_wt/deg + s_tt/deg ; doc = s_wd/deg + s_td/deg
// ---------------------------------------------------------------------------
__global__ void finalize_kernel(float* __restrict__ out) {
    int tt = blockIdx.x * blockDim.x + threadIdx.x;      // one float4 per thread
    const int total = (NW + NT + ND) * (DO_ / 4);
    if (tt >= total) return;
    int row = tt >> 5;
    int c   = (tt & 31) * 4;

    float4 v;
    if (row < NW) {
        float d = g_scratch[OFF_DEG_WW + row];
        float inv = d > 0.f ? 1.0f / d : 0.0f;
        float4 s = *reinterpret_cast<const float4*>(g_scratch + OFF_S_WW + (size_t)row * DO_ + c);
        v = make_float4(s.x * inv, s.y * inv, s.z * inv, s.w * inv);
    } else if (row < NW + NT) {
        int r = row - NW;
        float d1 = g_scratch[OFF_DEG_WT + r];
        float d2 = g_scratch[OFF_DEG_TT + r];
        float i1 = d1 > 0.f ? 1.0f / d1 : 0.0f;
        float i2 = d2 > 0.f ? 1.0f / d2 : 0.0f;
        float4 s1 = *reinterpret_cast<const float4*>(g_scratch + OFF_S_WT + (size_t)r * DO_ + c);
        float4 s2 = *reinterpret_cast<const float4*>(g_scratch + OFF_S_TT + (size_t)r * DO_ + c);
        v = make_float4(s1.x * i1 + s2.x * i2, s1.y * i1 + s2.y * i2,
                        s1.z * i1 + s2.z * i2, s1.w * i1 + s2.w * i2);
    } else {
        int r = row - NW - NT;
        float d1 = g_scratch[OFF_DEG_WD + r];
        float d2 = g_scratch[OFF_DEG_TD + r];
        float i1 = d1 > 0.f ? 1.0f / d1 : 0.0f;
        float i2 = d2 > 0.f ? 1.0f / d2 : 0.0f;
        float4 s1 = *reinterpret_cast<const float4*>(g_scratch + OFF_S_WD + (size_t)r * DO_ + c);
        float4 s2 = *reinterpret_cast<const float4*>(g_scratch + OFF_S_TD + (size_t)r * DO_ + c);
        v = make_float4(s1.x * i1 + s2.x * i2, s1.y * i1 + s2.y * i2,
                        s1.z * i1 + s2.z * i2, s1.w * i1 + s2.w * i2);
    }
    *reinterpret_cast<float4*>(out + (size_t)row * DO_ + c) = v;
}

// ---------------------------------------------------------------------------
// Launch
// ---------------------------------------------------------------------------
extern "C" void kernel_launch(void* const* d_in, const int* in_sizes, int n_in,
                              void* d_out, int out_size) {
    const float* feat_word  = (const float*)d_in[0];
    const float* feat_topic = (const float*)d_in[1];

    const int*   ww_src = (const int*)d_in[2];
    const int*   ww_dst = (const int*)d_in[3];
    const float* ww_w   = (const float*)d_in[4];
    const int*   wt_src = (const int*)d_in[5];
    const int*   wt_dst = (const int*)d_in[6];
    const float* wt_w   = (const float*)d_in[7];
    const int*   wd_src = (const int*)d_in[8];
    const int*   wd_dst = (const int*)d_in[9];
    const float* wd_w   = (const float*)d_in[10];
    const int*   td_src = (const int*)d_in[11];
    const int*   td_dst = (const int*)d_in[12];
    const float* td_w   = (const float*)d_in[13];
    const int*   tt_src = (const int*)d_in[14];
    const int*   tt_dst = (const int*)d_in[15];
    const float* tt_w   = (const float*)d_in[16];

    const float* W_ww = (const float*)d_in[17];
    const float* b_ww = (const float*)d_in[18];
    const float* W_wt = (const float*)d_in[19];
    const float* b_wt = (const float*)d_in[20];
    const float* W_wd = (const float*)d_in[21];
    const float* b_wd = (const float*)d_in[22];
    const float* W_td = (const float*)d_in[23];
    const float* b_td = (const float*)d_in[24];
    const float* W_tt = (const float*)d_in[25];
    const float* b_tt = (const float*)d_in[26];

    const int E_ww = in_sizes[2];
    const int E_wt = in_sizes[5];
    const int E_wd = in_sizes[8];
    const int E_td = in_sizes[11];
    const int E_tt = in_sizes[14];

    // 1) zero accumulators + degrees
    zero_accum_kernel<<<1184, 256>>>();

    // 2) projections (tf32 tensor cores, fused per source node type)
    const int gw = (NW + BM - 1) / BM;   // 391
    const int gt = (NT + BM - 1) / BM;   // 16
    {
        GemmRel r0{W_ww, b_ww, OFF_WH_WW};
        GemmRel r1{W_wt, b_wt, OFF_WH_WT};
        GemmRel r2{W_wd, b_wd, OFF_WH_WD};
        dim3 grid(gw, 3);
        gemm_tf32_multi_kernel<<<grid, 256>>>(feat_word, r0, r1, r2, NW, 256);
    }
    {
        GemmRel r0{W_td, b_td, OFF_WH_TD};
        GemmRel r1{W_tt, b_tt, OFF_WH_TT};
        GemmRel r2{W_tt, b_tt, OFF_WH_TT};   // slot unused: gridDim.y == 2
        dim3 grid(gt, 2);
        gemm_tf32_multi_kernel<<<grid, 256>>>(feat_topic, r0, r1, r2, NT, 128);
    }

    // 3) fused edge aggregation: one launch, one warp per edge
    EdgeTable et;
    et.src[0] = ww_src; et.dst[0] = ww_dst; et.w[0] = ww_w;
    et.src[1] = wt_src; et.dst[1] = wt_dst; et.w[1] = wt_w;
    et.src[2] = wd_src; et.dst[2] = wd_dst; et.w[2] = wd_w;
    et.src[3] = td_src; et.dst[3] = td_dst; et.w[3] = td_w;
    et.src[4] = tt_src; et.dst[4] = tt_dst; et.w[4] = tt_w;
    et.wh[0] = OFF_WH_WW; et.s[0] = OFF_S_WW; et.deg[0] = OFF_DEG_WW;
    et.wh[1] = OFF_WH_WT; et.s[1] = OFF_S_WT; et.deg[1] = OFF_DEG_WT;
    et.wh[2] = OFF_WH_WD; et.s[2] = OFF_S_WD; et.deg[2] = OFF_DEG_WD;
    et.wh[3] = OFF_WH_TD; et.s[3] = OFF_S_TD; et.deg[3] = OFF_DEG_TD;
    et.wh[4] = OFF_WH_TT; et.s[4] = OFF_S_TT; et.deg[4] = OFF_DEG_TT;
    et.end[0] = E_ww;
    et.end[1] = et.end[0] + E_wt;
    et.end[2] = et.end[1] + E_wd;
    et.end[3] = et.end[2] + E_td;
    et.end[4] = et.end[3] + E_tt;
    const int total_warps = et.end[4];
    edge_agg_fused_kernel<<<(total_warps + 7) / 8, 256>>>(et);

    // 4) finalize
    const int total4 = (NW + NT + ND) * (DO_ / 4);
    finalize_kernel<<<(total4 + 255) / 256, 256>>>((float*)d_out);
}

// round 10
// speedup vs baseline: 1.4876x; 1.2248x over previous
#include <cuda_runtime.h>
#include <cstdint>
#include <cstddef>

// ---------------------------------------------------------------------------
// Problem constants
// ---------------------------------------------------------------------------
static constexpr int NW = 50000;   // words
static constexpr int NT = 2000;    // topics
static constexpr int ND = 50000;   // docs
static constexpr int DO_ = 128;    // output dim

// CSR node-index bases per relation (dst node spaces):
//   rel0 ww -> word  [0, NW)
//   rel1 wt -> topic [NW, NW+NT)
//   rel2 wd -> doc   [NW+NT, NW+NT+ND)
//   rel3 td -> doc   [NW+NT+ND, NW+NT+2ND)
//   rel4 tt -> topic [NW+NT+2ND, NW+NT+2ND+NT)
static constexpr int BASE0 = 0;
static constexpr int BASE1 = NW;
static constexpr int BASE2 = NW + NT;
static constexpr int BASE3 = NW + NT + ND;
static constexpr int BASE4 = NW + NT + 2 * ND;
static constexpr int NTOT  = NW + NT + 2 * ND + NT;     // 154000

static constexpr int REC_CAP = 2300000;                 // >= sum of E (2.1M) + margin

// ---------------------------------------------------------------------------
// Scratch: Wh projections (float) + CSR structures
// ---------------------------------------------------------------------------
static constexpr size_t OFF_WH_WW = 0;
static constexpr size_t OFF_WH_WT = OFF_WH_WW + (size_t)NW * DO_;
static constexpr size_t OFF_WH_WD = OFF_WH_WT + (size_t)NW * DO_;
static constexpr size_t OFF_WH_TD = OFF_WH_WD + (size_t)NW * DO_;
static constexpr size_t OFF_WH_TT = OFF_WH_TD + (size_t)NT * DO_;
static constexpr size_t WH_TOTAL  = OFF_WH_TT + (size_t)NT * DO_;

__device__ __align__(16) float g_scratch[WH_TOTAL];

__device__ int  g_cnt[NTOT];        // per-node edge count (degree)
__device__ int  g_incl[NTOT];       // inclusive block-scan workspace
__device__ int  g_start[NTOT];      // exclusive prefix = row start
__device__ int  g_start_mut[NTOT];  // mutable copy for scatter slot assignment
__device__ int  g_partials[256];    // block partial sums for the scan
__device__ __align__(8) uint2 g_recs[REC_CAP];   // packed {src, w_bits}

// ---------------------------------------------------------------------------
// Edge table (fused over 5 relations)
// ---------------------------------------------------------------------------
struct EdgeTable {
    const int*   src[5];
    const int*   dst[5];
    const float* w[5];
    int base[5];
    int end[5];            // inclusive prefix-sum of edge counts
};

// ---------------------------------------------------------------------------
// Build step 0: zero counters
// ---------------------------------------------------------------------------
__global__ void zero_cnt_kernel() {
    int i = blockIdx.x * blockDim.x + threadIdx.x;
    int stride = gridDim.x * blockDim.x;
    for (; i < NTOT; i += stride) g_cnt[i] = 0;
}

// ---------------------------------------------------------------------------
// Build step 1: histogram of destination degrees (thread per edge)
// ---------------------------------------------------------------------------
__global__ void hist_kernel(EdgeTable et) {
    int t = blockIdx.x * blockDim.x + threadIdx.x;
    if (t >= et.end[4]) return;
    int r = 0;
    #pragma unroll
    for (int i = 0; i < 4; i++) r += (t >= et.end[i]) ? 1 : 0;
    int e = t - (r > 0 ? et.end[r - 1] : 0);
    int dn = __ldg(et.dst[r] + e);
    atomicAdd(&g_cnt[et.base[r] + dn], 1);
}

// ---------------------------------------------------------------------------
// Build step 2: exclusive scan of g_cnt -> g_start (3 small kernels)
// ---------------------------------------------------------------------------
#define SCAN_B 1024
__global__ void scan1_kernel() {   // per-block inclusive scan + block totals
    __shared__ int sh[SCAN_B];
    int i = blockIdx.x * SCAN_B + threadIdx.x;
    int v = (i < NTOT) ? g_cnt[i] : 0;
    sh[threadIdx.x] = v;
    __syncthreads();
    #pragma unroll
    for (int off = 1; off < SCAN_B; off <<= 1) {
        int t = (threadIdx.x >= off) ? sh[threadIdx.x - off] : 0;
        __syncthreads();
        sh[threadIdx.x] += t;
        __syncthreads();
    }
    if (i < NTOT) g_incl[i] = sh[threadIdx.x];
    if (threadIdx.x == SCAN_B - 1) g_partials[blockIdx.x] = sh[SCAN_B - 1];
}

__global__ void scan2_kernel(int nblocks) {   // exclusive scan of partials (tiny)
    if (threadIdx.x == 0 && blockIdx.x == 0) {
        int run = 0;
        for (int b = 0; b < nblocks; b++) {
            int t = g_partials[b];
            g_partials[b] = run;
            run += t;
        }
    }
}

__global__ void scan3_kernel() {   // start = incl - cnt + block_offset ; copy to mut
    int i = blockIdx.x * SCAN_B + threadIdx.x;
    if (i >= NTOT) return;
    int s = g_incl[i] - g_cnt[i] + g_partials[blockIdx.x];
    g_start[i] = s;
    g_start_mut[i] = s;
}

// ---------------------------------------------------------------------------
// Build step 3: scatter edge records into CSR slots (thread per edge)
// ---------------------------------------------------------------------------
__global__ void scatter_kernel(EdgeTable et) {
    int t = blockIdx.x * blockDim.x + threadIdx.x;
    if (t >= et.end[4]) return;
    int r = 0;
    #pragma unroll
    for (int i = 0; i < 4; i++) r += (t >= et.end[i]) ? 1 : 0;
    int e = t - (r > 0 ? et.end[r - 1] : 0);
    int   sn = __ldg(et.src[r] + e);
    int   dn = __ldg(et.dst[r] + e);
    float ew = __ldg(et.w[r] + e);
    int pos = atomicAdd(&g_start_mut[et.base[r] + dn], 1);
    if (pos < REC_CAP)
        g_recs[pos] = make_uint2((unsigned)sn, __float_as_uint(ew));
}

// ---------------------------------------------------------------------------
// Gather: one warp per output row. Accumulate in registers, divide by degree,
// sum across relations, write d_out directly (finalize fused).
// ---------------------------------------------------------------------------
__device__ __forceinline__ float4 accum_rel(int gidx, size_t wh_off, int lane) {
    int s = __ldg(&g_start[gidx]);
    int d = __ldg(&g_cnt[gidx]);
    float4 acc = make_float4(0.f, 0.f, 0.f, 0.f);
    const float* wh = g_scratch + wh_off;
    int k = 0;
    for (; k + 1 < d; k += 2) {
        uint2 r0 = __ldg(&g_recs[s + k]);
        uint2 r1 = __ldg(&g_recs[s + k + 1]);
        float w0 = __uint_as_float(r0.y);
        float w1 = __uint_as_float(r1.y);
        const float4* row0 = reinterpret_cast<const float4*>(wh + (size_t)r0.x * DO_);
        const float4* row1 = reinterpret_cast<const float4*>(wh + (size_t)r1.x * DO_);
        float4 v0 = __ldg(row0 + lane);
        float4 v1 = __ldg(row1 + lane);
        acc.x += v0.x * w0 + v1.x * w1;
        acc.y += v0.y * w0 + v1.y * w1;
        acc.z += v0.z * w0 + v1.z * w1;
        acc.w += v0.w * w0 + v1.w * w1;
    }
    if (k < d) {
        uint2 r0 = __ldg(&g_recs[s + k]);
        float w0 = __uint_as_float(r0.y);
        const float4* row0 = reinterpret_cast<const float4*>(wh + (size_t)r0.x * DO_);
        float4 v0 = __ldg(row0 + lane);
        acc.x += v0.x * w0;
        acc.y += v0.y * w0;
        acc.z += v0.z * w0;
        acc.w += v0.w * w0;
    }
    if (d > 0) {
        float inv = 1.0f / (float)d;
        acc.x *= inv; acc.y *= inv; acc.z *= inv; acc.w *= inv;
    }
    return acc;
}

__global__ void gather_kernel(float* __restrict__ out) {
    int warp = (int)(((size_t)blockIdx.x * blockDim.x + threadIdx.x) >> 5);
    int lane = threadIdx.x & 31;
    const int total_rows = NW + NT + ND;
    if (warp >= total_rows) return;

    float4 acc;
    if (warp < NW) {
        acc = accum_rel(BASE0 + warp, OFF_WH_WW, lane);
    } else if (warp < NW + NT) {
        int r = warp - NW;
        float4 a = accum_rel(BASE1 + r, OFF_WH_WT, lane);
        float4 b = accum_rel(BASE4 + r, OFF_WH_TT, lane);
        acc = make_float4(a.x + b.x, a.y + b.y, a.z + b.z, a.w + b.w);
    } else {
        int r = warp - NW - NT;
        float4 a = accum_rel(BASE2 + r, OFF_WH_WD, lane);
        float4 b = accum_rel(BASE3 + r, OFF_WH_TD, lane);
        acc = make_float4(a.x + b.x, a.y + b.y, a.z + b.z, a.w + b.w);
    }
    *reinterpret_cast<float4*>(out + (size_t)warp * DO_ + lane * 4) = acc;
}

// ---------------------------------------------------------------------------
// tf32 tensor-core GEMM + bias (fused over up to 3 relations via blockIdx.y)
//   C_r[M,128] = A[M,K] @ W_r[K,128] + b_r
// BM=128, BN=128, BK=32; 256 threads = 8 warps (2 x 4), warp tile 64x32.
// ---------------------------------------------------------------------------
#define BM 128
#define BN 128
#define BK 32

struct GemmRel {
    const float* W;
    const float* bias;
    size_t c_off;
};

__device__ __forceinline__ uint32_t f2tf32(float x) {
    uint32_t u;
    asm("cvt.rna.tf32.f32 %0, %1;" : "=r"(u) : "f"(x));
    return u;
}

__device__ __forceinline__ void mma_tf32(float c[4],
                                         uint32_t a0, uint32_t a1, uint32_t a2, uint32_t a3,
                                         uint32_t b0, uint32_t b1) {
    asm volatile("mma.sync.aligned.m16n8k8.row.col.f32.tf32.tf32.f32 "
                 "{%0,%1,%2,%3}, {%4,%5,%6,%7}, {%8,%9}, {%0,%1,%2,%3};"
                 : "+f"(c[0]), "+f"(c[1]), "+f"(c[2]), "+f"(c[3])
                 : "r"(a0), "r"(a1), "r"(a2), "r"(a3), "r"(b0), "r"(b1));
}

__global__ __launch_bounds__(256)
void gemm_tf32_multi_kernel(const float* __restrict__ A,
                            GemmRel r0, GemmRel r1, GemmRel r2,
                            int M, int K) {
    // As stored transposed [k][m], Bs row-major [k][n]; both padded +4 floats.
    __shared__ __align__(16) float As[BK][BM + 4];
    __shared__ __align__(16) float Bs[BK][BN + 4];

    const GemmRel rel = (blockIdx.y == 0) ? r0 : (blockIdx.y == 1) ? r1 : r2;
    const float* __restrict__ W    = rel.W;
    const float* __restrict__ bias = rel.bias;

    const int tid  = threadIdx.x;
    const int wid  = tid >> 5;
    const int lane = tid & 31;
    const int g    = lane >> 2;
    const int t    = lane & 3;
    const int wm   = (wid >> 2) * 64;
    const int wn   = (wid & 3) * 32;
    const int block_row = blockIdx.x * BM;

    float acc[4][4][4];
    #pragma unroll
    for (int mi = 0; mi < 4; mi++)
        #pragma unroll
        for (int ni = 0; ni < 4; ni++)
            #pragma unroll
            for (int c = 0; c < 4; c++) acc[mi][ni][c] = 0.f;

    for (int k0 = 0; k0 < K; k0 += BK) {
        // --- stage A tile: 128 rows x 32 cols -> As[k][m] (1024 float4) ---
        #pragma unroll
        for (int l = 0; l < 4; l++) {
            int idx = tid + l * 256;         // 0..1023
            int r   = idx >> 3;              // 0..127 (row within tile)
            int c4  = idx & 7;               // 0..7   (float4 within 32 cols)
            int grow = block_row + r;
            float4 v = make_float4(0.f, 0.f, 0.f, 0.f);
            if (grow < M)
                v = *reinterpret_cast<const float4*>(A + (size_t)grow * K + k0 + c4 * 4);
            As[c4 * 4 + 0][r] = __uint_as_float(f2tf32(v.x));
            As[c4 * 4 + 1][r] = __uint_as_float(f2tf32(v.y));
            As[c4 * 4 + 2][r] = __uint_as_float(f2tf32(v.z));
            As[c4 * 4 + 3][r] = __uint_as_float(f2tf32(v.w));
        }
        // --- stage W tile: 32 rows x 128 cols -> Bs[k][n] (1024 float4) ---
        #pragma unroll
        for (int l = 0; l < 4; l++) {
            int idx = tid + l * 256;         // 0..1023
            int r   = idx >> 5;              // 0..31
            int c4  = idx & 31;              // 0..31
            float4 v = *reinterpret_cast<const float4*>(W + (size_t)(k0 + r) * BN + c4 * 4);
            float4 o;
            o.x = __uint_as_float(f2tf32(v.x));
            o.y = __uint_as_float(f2tf32(v.y));
            o.z = __uint_as_float(f2tf32(v.z));
            o.w = __uint_as_float(f2tf32(v.w));
            *reinterpret_cast<float4*>(&Bs[r][c4 * 4]) = o;
        }
        __syncthreads();

        #pragma unroll
        for (int ks = 0; ks < BK; ks += 8) {
            uint32_t bf[4][2];
            #pragma unroll
            for (int ni = 0; ni < 4; ni++) {
                int n = wn + ni * 8 + g;
                bf[ni][0] = __float_as_uint(Bs[ks + t][n]);
                bf[ni][1] = __float_as_uint(Bs[ks + t + 4][n]);
            }
            #pragma unroll
            for (int mi = 0; mi < 4; mi++) {
                int m = wm + mi * 16 + g;
                uint32_t a0 = __float_as_uint(As[ks + t][m]);
                uint32_t a1 = __float_as_uint(As[ks + t][m + 8]);
                uint32_t a2 = __float_as_uint(As[ks + t + 4][m]);
                uint32_t a3 = __float_as_uint(As[ks + t + 4][m + 8]);
                #pragma unroll
                for (int ni = 0; ni < 4; ni++)
                    mma_tf32(acc[mi][ni], a0, a1, a2, a3, bf[ni][0], bf[ni][1]);
            }
        }
        __syncthreads();
    }

    float* C = g_scratch + rel.c_off;
    #pragma unroll
    for (int mi = 0; mi < 4; mi++) {
        #pragma unroll
        for (int ni = 0; ni < 4; ni++) {
            int col  = wn + ni * 8 + 2 * t;
            float b0 = bias[col], b1 = bias[col + 1];
            int row0 = block_row + wm + mi * 16 + g;
            int row1 = row0 + 8;
            if (row0 < M) {
                float2 v0 = make_float2(acc[mi][ni][0] + b0, acc[mi][ni][1] + b1);
                *reinterpret_cast<float2*>(C + (size_t)row0 * BN + col) = v0;
            }
            if (row1 < M) {
                float2 v1 = make_float2(acc[mi][ni][2] + b0, acc[mi][ni][3] + b1);
                *reinterpret_cast<float2*>(C + (size_t)row1 * BN + col) = v1;
            }
        }
    }
}

// ---------------------------------------------------------------------------
// Launch
// ---------------------------------------------------------------------------
extern "C" void kernel_launch(void* const* d_in, const int* in_sizes, int n_in,
                              void* d_out, int out_size) {
    const float* feat_word  = (const float*)d_in[0];
    const float* feat_topic = (const float*)d_in[1];

    const int*   ww_src = (const int*)d_in[2];
    const int*   ww_dst = (const int*)d_in[3];
    const float* ww_w   = (const float*)d_in[4];
    const int*   wt_src = (const int*)d_in[5];
    const int*   wt_dst = (const int*)d_in[6];
    const float* wt_w   = (const float*)d_in[7];
    const int*   wd_src = (const int*)d_in[8];
    const int*   wd_dst = (const int*)d_in[9];
    const float* wd_w   = (const float*)d_in[10];
    const int*   td_src = (const int*)d_in[11];
    const int*   td_dst = (const int*)d_in[12];
    const float* td_w   = (const float*)d_in[13];
    const int*   tt_src = (const int*)d_in[14];
    const int*   tt_dst = (const int*)d_in[15];
    const float* tt_w   = (const float*)d_in[16];

    const float* W_ww = (const float*)d_in[17];
    const float* b_ww = (const float*)d_in[18];
    const float* W_wt = (const float*)d_in[19];
    const float* b_wt = (const float*)d_in[20];
    const float* W_wd = (const float*)d_in[21];
    const float* b_wd = (const float*)d_in[22];
    const float* W_td = (const float*)d_in[23];
    const float* b_td = (const float*)d_in[24];
    const float* W_tt = (const float*)d_in[25];
    const float* b_tt = (const float*)d_in[26];

    const int E_ww = in_sizes[2];
    const int E_wt = in_sizes[5];
    const int E_wd = in_sizes[8];
    const int E_td = in_sizes[11];
    const int E_tt = in_sizes[14];

    EdgeTable et;
    et.src[0] = ww_src; et.dst[0] = ww_dst; et.w[0] = ww_w; et.base[0] = BASE0;
    et.src[1] = wt_src; et.dst[1] = wt_dst; et.w[1] = wt_w; et.base[1] = BASE1;
    et.src[2] = wd_src; et.dst[2] = wd_dst; et.w[2] = wd_w; et.base[2] = BASE2;
    et.src[3] = td_src; et.dst[3] = td_dst; et.w[3] = td_w; et.base[3] = BASE3;
    et.src[4] = tt_src; et.dst[4] = tt_dst; et.w[4] = tt_w; et.base[4] = BASE4;
    et.end[0] = E_ww;
    et.end[1] = et.end[0] + E_wt;
    et.end[2] = et.end[1] + E_wd;
    et.end[3] = et.end[2] + E_td;
    et.end[4] = et.end[3] + E_tt;
    const int E_total = et.end[4];

    // --- CSR build ---
    zero_cnt_kernel<<<152, 1024>>>();
    hist_kernel<<<(E_total + 255) / 256, 256>>>(et);
    const int scan_blocks = (NTOT + SCAN_B - 1) / SCAN_B;   // 151
    scan1_kernel<<<scan_blocks, SCAN_B>>>();
    scan2_kernel<<<1, 32>>>(scan_blocks);
    scan3_kernel<<<scan_blocks, SCAN_B>>>();
    scatter_kernel<<<(E_total + 255) / 256, 256>>>(et);

    // --- projections (tf32 tensor cores, fused per source node type) ---
    const int gw = (NW + BM - 1) / BM;   // 391
    const int gt = (NT + BM - 1) / BM;   // 16
    {
        GemmRel r0{W_ww, b_ww, OFF_WH_WW};
        GemmRel r1{W_wt, b_wt, OFF_WH_WT};
        GemmRel r2{W_wd, b_wd, OFF_WH_WD};
        dim3 grid(gw, 3);
        gemm_tf32_multi_kernel<<<grid, 256>>>(feat_word, r0, r1, r2, NW, 256);
    }
    {
        GemmRel r0{W_td, b_td, OFF_WH_TD};
        GemmRel r1{W_tt, b_tt, OFF_WH_TT};
        GemmRel r2{W_tt, b_tt, OFF_WH_TT};   // slot unused: gridDim.y == 2
        dim3 grid(gt, 2);
        gemm_tf32_multi_kernel<<<grid, 256>>>(feat_topic, r0, r1, r2, NT, 128);
    }

    // --- gather + finalize (one warp per output row) ---
    const int total_rows = NW + NT + ND;
    const int gather_blocks = (total_rows * 32 + 255) / 256;
    gather_kernel<<<gather_blocks, 256>>>((float*)d_out);
}

// round 17
// speedup vs baseline: 1.6670x; 1.1206x over previous
#include <cuda_runtime.h>
#include <cstdint>
#include <cstddef>

// ---------------------------------------------------------------------------
// Problem constants
// ---------------------------------------------------------------------------
static constexpr int NW = 50000;   // words
static constexpr int NT = 2000;    // topics
static constexpr int ND = 50000;   // docs
static constexpr int DO_ = 128;    // output dim

// CSR node-index bases per relation (dst node spaces)
static constexpr int BASE0 = 0;
static constexpr int BASE1 = NW;
static constexpr int BASE2 = NW + NT;
static constexpr int BASE3 = NW + NT + ND;
static constexpr int BASE4 = NW + NT + 2 * ND;
static constexpr int NTOT  = NW + NT + 2 * ND + NT;     // 154000

static constexpr int REC_CAP = 2300000;                 // >= sum of E (2.1M) + margin

// ---------------------------------------------------------------------------
// Scratch: Wh projections (float) + CSR structures
// ---------------------------------------------------------------------------
static constexpr size_t OFF_WH_WW = 0;
static constexpr size_t OFF_WH_WT = OFF_WH_WW + (size_t)NW * DO_;
static constexpr size_t OFF_WH_WD = OFF_WH_WT + (size_t)NW * DO_;
static constexpr size_t OFF_WH_TD = OFF_WH_WD + (size_t)NW * DO_;
static constexpr size_t OFF_WH_TT = OFF_WH_TD + (size_t)NT * DO_;
static constexpr size_t WH_TOTAL  = OFF_WH_TT + (size_t)NT * DO_;

__device__ __align__(16) float g_scratch[WH_TOTAL];

__device__ int  g_cnt[NTOT];
__device__ int  g_incl[NTOT];
__device__ int  g_start[NTOT];
__device__ int  g_start_mut[NTOT];
__device__ int  g_partials[256];
__device__ __align__(8) uint2 g_recs[REC_CAP];   // packed {src, w_bits}

// ---------------------------------------------------------------------------
// Edge table (fused over 5 relations)
// ---------------------------------------------------------------------------
struct EdgeTable {
    const int*   src[5];
    const int*   dst[5];
    const float* w[5];
    int base[5];
    int end[5];
};

__global__ void zero_cnt_kernel() {
    int i = blockIdx.x * blockDim.x + threadIdx.x;
    int stride = gridDim.x * blockDim.x;
    for (; i < NTOT; i += stride) g_cnt[i] = 0;
}

__global__ void hist_kernel(EdgeTable et) {
    int t = blockIdx.x * blockDim.x + threadIdx.x;
    if (t >= et.end[4]) return;
    int r = 0;
    #pragma unroll
    for (int i = 0; i < 4; i++) r += (t >= et.end[i]) ? 1 : 0;
    int e = t - (r > 0 ? et.end[r - 1] : 0);
    int dn = __ldg(et.dst[r] + e);
    atomicAdd(&g_cnt[et.base[r] + dn], 1);
}

// ---------------------------------------------------------------------------
// Exclusive scan of g_cnt -> g_start (3 kernels; scan2 parallel)
// ---------------------------------------------------------------------------
#define SCAN_B 1024
__global__ void scan1_kernel() {
    __shared__ int sh[SCAN_B];
    int i = blockIdx.x * SCAN_B + threadIdx.x;
    int v = (i < NTOT) ? g_cnt[i] : 0;
    sh[threadIdx.x] = v;
    __syncthreads();
    #pragma unroll
    for (int off = 1; off < SCAN_B; off <<= 1) {
        int t = (threadIdx.x >= off) ? sh[threadIdx.x - off] : 0;
        __syncthreads();
        sh[threadIdx.x] += t;
        __syncthreads();
    }
    if (i < NTOT) g_incl[i] = sh[threadIdx.x];
    if (threadIdx.x == SCAN_B - 1) g_partials[blockIdx.x] = sh[SCAN_B - 1];
}

__global__ void scan2_kernel(int nblocks) {   // parallel scan over <=256 partials
    __shared__ int sh[256];
    int i = threadIdx.x;
    int v = (i < nblocks) ? g_partials[i] : 0;
    sh[i] = v;
    __syncthreads();
    #pragma unroll
    for (int off = 1; off < 256; off <<= 1) {
        int t = (i >= off) ? sh[i - off] : 0;
        __syncthreads();
        sh[i] += t;
        __syncthreads();
    }
    if (i < nblocks) g_partials[i] = sh[i] - v;   // exclusive = inclusive - self
}

__global__ void scan3_kernel() {
    int i = blockIdx.x * SCAN_B + threadIdx.x;
    if (i >= NTOT) return;
    int s = g_incl[i] - g_cnt[i] + g_partials[blockIdx.x];
    g_start[i] = s;
    g_start_mut[i] = s;
}

__global__ void scatter_kernel(EdgeTable et) {
    int t = blockIdx.x * blockDim.x + threadIdx.x;
    if (t >= et.end[4]) return;
    int r = 0;
    #pragma unroll
    for (int i = 0; i < 4; i++) r += (t >= et.end[i]) ? 1 : 0;
    int e = t - (r > 0 ? et.end[r - 1] : 0);
    int   sn = __ldg(et.src[r] + e);
    int   dn = __ldg(et.dst[r] + e);
    float ew = __ldg(et.w[r] + e);
    int pos = atomicAdd(&g_start_mut[et.base[r] + dn], 1);
    if (pos < REC_CAP)
        g_recs[pos] = make_uint2((unsigned)sn, __float_as_uint(ew));
}

// ---------------------------------------------------------------------------
// Gather: one warp per output row, 4-wide software pipeline on records.
// ---------------------------------------------------------------------------
__device__ __forceinline__ float4 accum_rel(int gidx, size_t wh_off, int lane) {
    int s = __ldg(&g_start[gidx]);
    int d = __ldg(&g_cnt[gidx]);
    const float* wh = g_scratch + wh_off;
    float4 acc = make_float4(0.f, 0.f, 0.f, 0.f);

    uint2 rec[4];
    #pragma unroll
    for (int j = 0; j < 4; j++)
        if (j < d) rec[j] = __ldg(&g_recs[s + j]);

    for (int k = 0; k < d; k += 4) {
        uint2 cur[4];
        #pragma unroll
        for (int j = 0; j < 4; j++) cur[j] = rec[j];
        // prefetch next group of records (overlaps with row loads below)
        #pragma unroll
        for (int j = 0; j < 4; j++)
            if (k + 4 + j < d) rec[j] = __ldg(&g_recs[s + k + 4 + j]);
        // 4 independent row loads -> high MLP
        float4 v[4];
        #pragma unroll
        for (int j = 0; j < 4; j++)
            if (k + j < d)
                v[j] = __ldg(reinterpret_cast<const float4*>(wh + (size_t)cur[j].x * DO_) + lane);
        #pragma unroll
        for (int j = 0; j < 4; j++) {
            if (k + j < d) {
                float w = __uint_as_float(cur[j].y);
                acc.x += v[j].x * w;
                acc.y += v[j].y * w;
                acc.z += v[j].z * w;
                acc.w += v[j].w * w;
            }
        }
    }
    if (d > 0) {
        float inv = 1.0f / (float)d;
        acc.x *= inv; acc.y *= inv; acc.z *= inv; acc.w *= inv;
    }
    return acc;
}

__global__ void gather_kernel(float* __restrict__ out) {
    int warp = (int)(((size_t)blockIdx.x * blockDim.x + threadIdx.x) >> 5);
    int lane = threadIdx.x & 31;
    const int total_rows = NW + NT + ND;
    if (warp >= total_rows) return;

    float4 acc;
    if (warp < NW) {
        acc = accum_rel(BASE0 + warp, OFF_WH_WW, lane);
    } else if (warp < NW + NT) {
        int r = warp - NW;
        float4 a = accum_rel(BASE1 + r, OFF_WH_WT, lane);
        float4 b = accum_rel(BASE4 + r, OFF_WH_TT, lane);
        acc = make_float4(a.x + b.x, a.y + b.y, a.z + b.z, a.w + b.w);
    } else {
        int r = warp - NW - NT;
        float4 a = accum_rel(BASE2 + r, OFF_WH_WD, lane);
        float4 b = accum_rel(BASE3 + r, OFF_WH_TD, lane);
        acc = make_float4(a.x + b.x, a.y + b.y, a.z + b.z, a.w + b.w);
    }
    *reinterpret_cast<float4*>(out + (size_t)warp * DO_ + lane * 4) = acc;
}

// ---------------------------------------------------------------------------
// tf32 tensor-core GEMM + bias, register double-buffered.
// BM=128, BN=128, BK=32; 256 threads = 8 warps (2 x 4), warp tile 64x32.
// ---------------------------------------------------------------------------
#define BM 128
#define BN 128
#define BK 32

struct GemmRel {
    const float* W;
    const float* bias;
    size_t c_off;
};

__device__ __forceinline__ uint32_t f2tf32(float x) {
    uint32_t u;
    asm("cvt.rna.tf32.f32 %0, %1;" : "=r"(u) : "f"(x));
    return u;
}

__device__ __forceinline__ void mma_tf32(float c[4],
                                         uint32_t a0, uint32_t a1, uint32_t a2, uint32_t a3,
                                         uint32_t b0, uint32_t b1) {
    asm volatile("mma.sync.aligned.m16n8k8.row.col.f32.tf32.tf32.f32 "
                 "{%0,%1,%2,%3}, {%4,%5,%6,%7}, {%8,%9}, {%0,%1,%2,%3};"
                 : "+f"(c[0]), "+f"(c[1]), "+f"(c[2]), "+f"(c[3])
                 : "r"(a0), "r"(a1), "r"(a2), "r"(a3), "r"(b0), "r"(b1));
}

__global__ __launch_bounds__(256)
void gemm_tf32_multi_kernel(const float* __restrict__ A,
                            GemmRel r0, GemmRel r1, GemmRel r2,
                            int M, int K) {
    __shared__ __align__(16) float As[BK][BM + 4];
    __shared__ __align__(16) float Bs[BK][BN + 4];

    const GemmRel rel = (blockIdx.y == 0) ? r0 : (blockIdx.y == 1) ? r1 : r2;
    const float* __restrict__ W    = rel.W;
    const float* __restrict__ bias = rel.bias;

    const int tid  = threadIdx.x;
    const int wid  = tid >> 5;
    const int lane = tid & 31;
    const int g    = lane >> 2;
    const int t    = lane & 3;
    const int wm   = (wid >> 2) * 64;
    const int wn   = (wid & 3) * 32;
    const int block_row = blockIdx.x * BM;

    // staging registers for the double buffer
    float4 va[4], vb[4];

    auto load_tile = [&](int k0) {
        #pragma unroll
        for (int l = 0; l < 4; l++) {
            int idx  = tid + l * 256;        // 0..1023
            int r    = idx >> 3;             // 0..127
            int c4   = idx & 7;              // 0..7
            int grow = block_row + r;
            va[l] = make_float4(0.f, 0.f, 0.f, 0.f);
            if (grow < M)
                va[l] = *reinterpret_cast<const float4*>(A + (size_t)grow * K + k0 + c4 * 4);
        }
        #pragma unroll
        for (int l = 0; l < 4; l++) {
            int idx = tid + l * 256;         // 0..1023
            int r   = idx >> 5;              // 0..31
            int c4  = idx & 31;              // 0..31
            vb[l] = *reinterpret_cast<const float4*>(W + (size_t)(k0 + r) * BN + c4 * 4);
        }
    };

    auto store_tile = [&]() {
        #pragma unroll
        for (int l = 0; l < 4; l++) {
            int idx = tid + l * 256;
            int r   = idx >> 3;
            int c4  = idx & 7;
            As[c4 * 4 + 0][r] = __uint_as_float(f2tf32(va[l].x));
            As[c4 * 4 + 1][r] = __uint_as_float(f2tf32(va[l].y));
            As[c4 * 4 + 2][r] = __uint_as_float(f2tf32(va[l].z));
            As[c4 * 4 + 3][r] = __uint_as_float(f2tf32(va[l].w));
        }
        #pragma unroll
        for (int l = 0; l < 4; l++) {
            int idx = tid + l * 256;
            int r   = idx >> 5;
            int c4  = idx & 31;
            float4 o;
            o.x = __uint_as_float(f2tf32(vb[l].x));
            o.y = __uint_as_float(f2tf32(vb[l].y));
            o.z = __uint_as_float(f2tf32(vb[l].z));
            o.w = __uint_as_float(f2tf32(vb[l].w));
            *reinterpret_cast<float4*>(&Bs[r][c4 * 4]) = o;
        }
    };

    float acc[4][4][4];
    #pragma unroll
    for (int mi = 0; mi < 4; mi++)
        #pragma unroll
        for (int ni = 0; ni < 4; ni++)
            #pragma unroll
            for (int c = 0; c < 4; c++) acc[mi][ni][c] = 0.f;

    auto compute_tile = [&]() {
        #pragma unroll
        for (int ks = 0; ks < BK; ks += 8) {
            uint32_t bf[4][2];
            #pragma unroll
            for (int ni = 0; ni < 4; ni++) {
                int n = wn + ni * 8 + g;
                bf[ni][0] = __float_as_uint(Bs[ks + t][n]);
                bf[ni][1] = __float_as_uint(Bs[ks + t + 4][n]);
            }
            #pragma unroll
            for (int mi = 0; mi < 4; mi++) {
                int m = wm + mi * 16 + g;
                uint32_t a0 = __float_as_uint(As[ks + t][m]);
                uint32_t a1 = __float_as_uint(As[ks + t][m + 8]);
                uint32_t a2 = __float_as_uint(As[ks + t + 4][m]);
                uint32_t a3 = __float_as_uint(As[ks + t + 4][m + 8]);
                #pragma unroll
                for (int ni = 0; ni < 4; ni++)
                    mma_tf32(acc[mi][ni], a0, a1, a2, a3, bf[ni][0], bf[ni][1]);
            }
        }
    };

    // prologue: stage tile 0
    load_tile(0);
    store_tile();
    __syncthreads();

    for (int k0 = BK; k0 < K; k0 += BK) {
        load_tile(k0);     // global loads overlap with compute below
        compute_tile();
        __syncthreads();   // all warps done reading smem
        store_tile();
        __syncthreads();   // smem ready
    }
    compute_tile();        // last tile

    // epilogue: add bias, write C
    float* C = g_scratch + rel.c_off;
    #pragma unroll
    for (int mi = 0; mi < 4; mi++) {
        #pragma unroll
        for (int ni = 0; ni < 4; ni++) {
            int col  = wn + ni * 8 + 2 * t;
            float b0 = bias[col], b1 = bias[col + 1];
            int row0 = block_row + wm + mi * 16 + g;
            int row1 = row0 + 8;
            if (row0 < M) {
                float2 v0 = make_float2(acc[mi][ni][0] + b0, acc[mi][ni][1] + b1);
                *reinterpret_cast<float2*>(C + (size_t)row0 * BN + col) = v0;
            }
            if (row1 < M) {
                float2 v1 = make_float2(acc[mi][ni][2] + b0, acc[mi][ni][3] + b1);
                *reinterpret_cast<float2*>(C + (size_t)row1 * BN + col) = v1;
            }
        }
    }
}

// ---------------------------------------------------------------------------
// Launch
// ---------------------------------------------------------------------------
extern "C" void kernel_launch(void* const* d_in, const int* in_sizes, int n_in,
                              void* d_out, int out_size) {
    const float* feat_word  = (const float*)d_in[0];
    const float* feat_topic = (const float*)d_in[1];

    const int*   ww_src = (const int*)d_in[2];
    const int*   ww_dst = (const int*)d_in[3];
    const float* ww_w   = (const float*)d_in[4];
    const int*   wt_src = (const int*)d_in[5];
    const int*   wt_dst = (const int*)d_in[6];
    const float* wt_w   = (const float*)d_in[7];
    const int*   wd_src = (const int*)d_in[8];
    const int*   wd_dst = (const int*)d_in[9];
    const float* wd_w   = (const float*)d_in[10];
    const int*   td_src = (const int*)d_in[11];
    const int*   td_dst = (const int*)d_in[12];
    const float* td_w   = (const float*)d_in[13];
    const int*   tt_src = (const int*)d_in[14];
    const int*   tt_dst = (const int*)d_in[15];
    const float* tt_w   = (const float*)d_in[16];

    const float* W_ww = (const float*)d_in[17];
    const float* b_ww = (const float*)d_in[18];
    const float* W_wt = (const float*)d_in[19];
    const float* b_wt = (const float*)d_in[20];
    const float* W_wd = (const float*)d_in[21];
    const float* b_wd = (const float*)d_in[22];
    const float* W_td = (const float*)d_in[23];
    const float* b_td = (const float*)d_in[24];
    const float* W_tt = (const float*)d_in[25];
    const float* b_tt = (const float*)d_in[26];

    const int E_ww = in_sizes[2];
    const int E_wt = in_sizes[5];
    const int E_wd = in_sizes[8];
    const int E_td = in_sizes[11];
    const int E_tt = in_sizes[14];

    EdgeTable et;
    et.src[0] = ww_src; et.dst[0] = ww_dst; et.w[0] = ww_w; et.base[0] = BASE0;
    et.src[1] = wt_src; et.dst[1] = wt_dst; et.w[1] = wt_w; et.base[1] = BASE1;
    et.src[2] = wd_src; et.dst[2] = wd_dst; et.w[2] = wd_w; et.base[2] = BASE2;
    et.src[3] = td_src; et.dst[3] = td_dst; et.w[3] = td_w; et.base[3] = BASE3;
    et.src[4] = tt_src; et.dst[4] = tt_dst; et.w[4] = tt_w; et.base[4] = BASE4;
    et.end[0] = E_ww;
    et.end[1] = et.end[0] + E_wt;
    et.end[2] = et.end[1] + E_wd;
    et.end[3] = et.end[2] + E_td;
    et.end[4] = et.end[3] + E_tt;
    const int E_total = et.end[4];

    // --- CSR build ---
    zero_cnt_kernel<<<152, 1024>>>();
    hist_kernel<<<(E_total + 255) / 256, 256>>>(et);
    const int scan_blocks = (NTOT + SCAN_B - 1) / SCAN_B;   // 151
    scan1_kernel<<<scan_blocks, SCAN_B>>>();
    scan2_kernel<<<1, 256>>>(scan_blocks);
    scan3_kernel<<<scan_blocks, SCAN_B>>>();
    scatter_kernel<<<(E_total + 255) / 256, 256>>>(et);

    // --- projections (tf32 tensor cores, fused per source node type) ---
    const int gw = (NW + BM - 1) / BM;   // 391
    const int gt = (NT + BM - 1) / BM;   // 16
    {
        GemmRel r0{W_ww, b_ww, OFF_WH_WW};
        GemmRel r1{W_wt, b_wt, OFF_WH_WT};
        GemmRel r2{W_wd, b_wd, OFF_WH_WD};
        dim3 grid(gw, 3);
        gemm_tf32_multi_kernel<<<grid, 256>>>(feat_word, r0, r1, r2, NW, 256);
    }
    {
        GemmRel r0{W_td, b_td, OFF_WH_TD};
        GemmRel r1{W_tt, b_tt, OFF_WH_TT};
        GemmRel r2{W_tt, b_tt, OFF_WH_TT};   // slot unused: gridDim.y == 2
        dim3 grid(gt, 2);
        gemm_tf32_multi_kernel<<<grid, 256>>>(feat_topic, r0, r1, r2, NT, 128);
    }

    // --- gather + finalize (one warp per output row) ---
    const int total_rows = NW + NT + ND;
    const int gather_blocks = (total_rows * 32 + 255) / 256;
    gather_kernel<<<gather_blocks, 256>>>((float*)d_out);
}